// round 3
// baseline (speedup 1.0000x reference)
#include <cuda_runtime.h>
#include <cstddef>

// Problem constants
static constexpr int MTOT = 64 * 4096;   // B*N rows
static constexpr int E    = 512;          // embedding dim (main GEMM K)
static constexpr int TOK  = 256;          // output tokens (GEMM N)
static constexpr int KS   = 56;           // small K: 1 (vis) + 4 (bbox) + 51 (kpts)

// Tiling
#define BM 128
#define BN 128
#define BK 16
#define TM 8
#define TN 8

__device__ __forceinline__ unsigned long long pack2(float x, float y) {
    unsigned long long r;
    asm("mov.b64 %0, {%1, %2};" : "=l"(r) : "f"(x), "f"(y));
    return r;
}
__device__ __forceinline__ void unpack2(unsigned long long v, float& x, float& y) {
    asm("mov.b64 {%0, %1}, %2;" : "=f"(x), "=f"(y) : "l"(v));
}
__device__ __forceinline__ unsigned long long ffma2(unsigned long long a,
                                                    unsigned long long b,
                                                    unsigned long long c) {
    unsigned long long d;
    asm("fma.rn.f32x2 %0, %1, %2, %3;" : "=l"(d) : "l"(a), "l"(b), "l"(c));
    return d;
}

__global__ __launch_bounds__(256, 2)
void seplin_kernel(const float* __restrict__ emb,
                   const float* __restrict__ vis,
                   const float* __restrict__ bbox,
                   const float* __restrict__ kpts,
                   const int* __restrict__ mask,        // bool -> int32 in harness
                   const float* __restrict__ appW,
                   const float* __restrict__ appB,
                   const float* __restrict__ stW,
                   const float* __restrict__ stB,
                   float* __restrict__ out)
{
    __shared__ float As[BK][BM + 4];
    __shared__ float Bs[BK][BN];
    __shared__ float A2s[8][BM + 4];
    __shared__ float W2s[8][BN];

    const int tid = threadIdx.x;
    const int tx  = tid & 15;     // 0..15 -> column group
    const int ty  = tid >> 4;     // 0..15 -> row group
    const int rowBase = blockIdx.y * BM;
    const int colBase = blockIdx.x * BN;
    const int r0 = rowBase + ty * TM;
    const int c0 = colBase + tx * TN;

    unsigned long long acc[TM][TN / 2];
#pragma unroll
    for (int i = 0; i < TM; i++)
#pragma unroll
        for (int j = 0; j < TN / 2; j++) acc[i][j] = 0ULL;

    // ---------------- Main GEMM over emb (K = 512) ----------------
    for (int kb = 0; kb < E; kb += BK) {
        // A tile: 128 rows x 16 k, 512 float4 loads
#pragma unroll
        for (int l = 0; l < 2; l++) {
            int idx = tid + l * 256;
            int m   = idx >> 2;       // 0..127
            int kq  = idx & 3;        // which float4 in row
            float4 v = *reinterpret_cast<const float4*>(
                &emb[(size_t)(rowBase + m) * E + kb + kq * 4]);
            As[kq * 4 + 0][m] = v.x;
            As[kq * 4 + 1][m] = v.y;
            As[kq * 4 + 2][m] = v.z;
            As[kq * 4 + 3][m] = v.w;
        }
        // B tile: 16 k x 128 cols
#pragma unroll
        for (int l = 0; l < 2; l++) {
            int idx = tid + l * 256;
            int k   = idx >> 5;       // 0..15
            int cq  = idx & 31;       // float4 within row
            float4 v = *reinterpret_cast<const float4*>(
                &appW[(size_t)(kb + k) * TOK + colBase + cq * 4]);
            *reinterpret_cast<float4*>(&Bs[k][cq * 4]) = v;
        }
        __syncthreads();

#pragma unroll
        for (int k = 0; k < BK; k++) {
            float4 a0 = *reinterpret_cast<const float4*>(&As[k][ty * TM]);
            float4 a1 = *reinterpret_cast<const float4*>(&As[k][ty * TM + 4]);
            float a[TM] = {a0.x, a0.y, a0.z, a0.w, a1.x, a1.y, a1.z, a1.w};
            const ulonglong2* bp =
                reinterpret_cast<const ulonglong2*>(&Bs[k][tx * TN]);
            ulonglong2 b01 = bp[0];
            ulonglong2 b23 = bp[1];
            unsigned long long bq[TN / 2] = {b01.x, b01.y, b23.x, b23.y};
#pragma unroll
            for (int i = 0; i < TM; i++) {
                unsigned long long ad = pack2(a[i], a[i]);
#pragma unroll
                for (int j = 0; j < TN / 2; j++)
                    acc[i][j] = ffma2(ad, bq[j], acc[i][j]);
            }
        }
        __syncthreads();
    }

    // -------- Small-K part: vis (1) + bbox (4) + kpts (51) = 56 --------
    for (int kb2 = 0; kb2 < KS; kb2 += 8) {
        // A2 tile: 128 rows x 8 k (gathered)
#pragma unroll
        for (int l = 0; l < 4; l++) {
            int idx  = tid + l * 256;
            int m    = idx >> 3;      // 0..127
            int kloc = idx & 7;
            int kk   = kb2 + kloc;
            int row  = rowBase + m;
            float v;
            if (kk == 0)      v = vis[row];
            else if (kk < 5)  v = bbox[(size_t)row * 4 + (kk - 1)];
            else              v = kpts[(size_t)row * 51 + (kk - 5)];
            A2s[kloc][m] = v;
        }
        // W2 tile: 8 k x 128 cols (gathered from appW row 512 / stW)
#pragma unroll
        for (int l = 0; l < 4; l++) {
            int idx  = tid + l * 256;
            int kloc = idx >> 7;      // 0..7
            int c    = idx & 127;
            int kk   = kb2 + kloc;
            float w = (kk == 0)
                          ? appW[(size_t)E * TOK + colBase + c]
                          : stW[(size_t)(kk - 1) * TOK + colBase + c];
            W2s[kloc][c] = w;
        }
        __syncthreads();

#pragma unroll
        for (int k = 0; k < 8; k++) {
            float4 a0 = *reinterpret_cast<const float4*>(&A2s[k][ty * TM]);
            float4 a1 = *reinterpret_cast<const float4*>(&A2s[k][ty * TM + 4]);
            float a[TM] = {a0.x, a0.y, a0.z, a0.w, a1.x, a1.y, a1.z, a1.w};
            const ulonglong2* bp =
                reinterpret_cast<const ulonglong2*>(&W2s[k][tx * TN]);
            ulonglong2 b01 = bp[0];
            ulonglong2 b23 = bp[1];
            unsigned long long bq[TN / 2] = {b01.x, b01.y, b23.x, b23.y};
#pragma unroll
            for (int i = 0; i < TM; i++) {
                unsigned long long ad = pack2(a[i], a[i]);
#pragma unroll
                for (int j = 0; j < TN / 2; j++)
                    acc[i][j] = ffma2(ad, bq[j], acc[i][j]);
            }
        }
        __syncthreads();
    }

    // ---------------- Epilogue: bias + mask + store ----------------
    float bias[TN];
#pragma unroll
    for (int j = 0; j < TN; j++) bias[j] = appB[c0 + j] + stB[c0 + j];

#pragma unroll
    for (int i = 0; i < TM; i++) {
        int row = r0 + i;
        float mk = (mask[row] != 0) ? 1.0f : 0.0f;
        float o[TN];
#pragma unroll
        for (int j = 0; j < TN / 2; j++)
            unpack2(acc[i][j], o[2 * j], o[2 * j + 1]);
        float4 w0 = make_float4((o[0] + bias[0]) * mk, (o[1] + bias[1]) * mk,
                                (o[2] + bias[2]) * mk, (o[3] + bias[3]) * mk);
        float4 w1 = make_float4((o[4] + bias[4]) * mk, (o[5] + bias[5]) * mk,
                                (o[6] + bias[6]) * mk, (o[7] + bias[7]) * mk);
        *reinterpret_cast<float4*>(&out[(size_t)row * TOK + c0])     = w0;
        *reinterpret_cast<float4*>(&out[(size_t)row * TOK + c0 + 4]) = w1;
    }
}

extern "C" void kernel_launch(void* const* d_in, const int* in_sizes, int n_in,
                              void* d_out, int out_size)
{
    const float* emb  = (const float*)d_in[0];
    const float* vis  = (const float*)d_in[1];
    const float* bbox = (const float*)d_in[2];
    const float* kpts = (const float*)d_in[3];
    const int*   mask = (const int*)d_in[4];
    const float* appW = (const float*)d_in[5];
    const float* appB = (const float*)d_in[6];
    const float* stW  = (const float*)d_in[7];
    const float* stB  = (const float*)d_in[8];

    dim3 grid(TOK / BN, MTOT / BM);   // (2, 2048)
    seplin_kernel<<<grid, 256>>>(emb, vis, bbox, kpts, mask,
                                 appW, appB, stW, stB, (float*)d_out);
    (void)in_sizes; (void)n_in; (void)out_size;
}

// round 5
// speedup vs baseline: 1.5040x; 1.5040x over previous
#include <cuda_runtime.h>
#include <cstdint>
#include <cstddef>

// ---------------- constants ----------------
static constexpr int BM = 128, BN = 128;
static constexpr int NCHUNK = 9;                 // K = 576 (568 + pad) in chunks of 64
static constexpr int GRID_M = 262144 / BM;       // 2048

// dynamic smem offsets
static constexpr uint32_t ST_AH = 0;             // A hi : 128 rows x 128B = 16KB
static constexpr uint32_t ST_AL = 16384;
static constexpr uint32_t ST_BH = 32768;         // B hi : 128 rows x 128B = 16KB
static constexpr uint32_t ST_BL = 49152;
static constexpr uint32_t STAGE_SZ = 65536;
static constexpr uint32_t OFF_BIAS = 131072;     // 128 floats
static constexpr uint32_t OFF_MASK = 131584;     // 128 ints
static constexpr uint32_t SMEM_TOTAL = 132096;

// prepacked swizzled B tile images (hi/lo): [chunk][n=0..255][k=0..63] bf16, 128B rows
__device__ uint32_t g_Bhi[NCHUNK * 8192];
__device__ uint32_t g_Blo[NCHUNK * 8192];

// ---------------- helpers ----------------
__device__ __forceinline__ uint32_t smem_u32(const void* p) {
    uint32_t a;
    asm("{ .reg .u64 t; cvta.to.shared.u64 t, %1; cvt.u32.u64 %0, t; }"
        : "=r"(a) : "l"(p));
    return a;
}
__device__ __forceinline__ unsigned short f2bf(float x) {
    unsigned short u;
    asm("cvt.rn.bf16.f32 %0, %1;" : "=h"(u) : "f"(x));
    return u;
}
#define SW128(o) ((o) ^ (((o) >> 3) & 0x70))

__device__ __forceinline__ void cp16(uint32_t dst, const void* src) {
    asm volatile("cp.async.cg.shared.global [%0], [%1], 16;"
                 :: "r"(dst), "l"(src) : "memory");
}
__device__ __forceinline__ void cp_commit() {
    asm volatile("cp.async.commit_group;" ::: "memory");
}
template <int N>
__device__ __forceinline__ void cp_wait() {
    asm volatile("cp.async.wait_group %0;" :: "n"(N) : "memory");
}
__device__ __forceinline__ void ldsm4(uint32_t* r, uint32_t a) {
    asm volatile("ldmatrix.sync.aligned.m8n8.x4.shared.b16 {%0,%1,%2,%3}, [%4];"
                 : "=r"(r[0]), "=r"(r[1]), "=r"(r[2]), "=r"(r[3]) : "r"(a));
}
__device__ __forceinline__ void mma16816(float& d0, float& d1, float& d2, float& d3,
                                         const uint32_t* a, uint32_t b0, uint32_t b1) {
    asm volatile(
        "mma.sync.aligned.m16n8k16.row.col.f32.bf16.bf16.f32 "
        "{%0,%1,%2,%3}, {%4,%5,%6,%7}, {%8,%9}, {%0,%1,%2,%3};"
        : "+f"(d0), "+f"(d1), "+f"(d2), "+f"(d3)
        : "r"(a[0]), "r"(a[1]), "r"(a[2]), "r"(a[3]), "r"(b0), "r"(b1));
}

// split fp32 -> (bf16 hi trunc, bf16 lo rn), two elements packed per u32
__device__ __forceinline__ void split2(float x0, float x1, uint32_t& hw, uint32_t& lw) {
    uint32_t xb0 = __float_as_uint(x0);
    uint32_t xb1 = __float_as_uint(x1);
    hw = (xb0 >> 16) | (xb1 & 0xFFFF0000u);
    float l0 = x0 - __uint_as_float(xb0 & 0xFFFF0000u);
    float l1 = x1 - __uint_as_float(xb1 & 0xFFFF0000u);
    lw = (uint32_t)f2bf(l0) | ((uint32_t)f2bf(l1) << 16);
}

// ---------------- pre-kernel: pack W hi/lo into swizzled K-major images ----------------
__device__ __forceinline__ float fetchW(int k, int n, const float* appW,
                                        const float* stW) {
    if (k <= 512) return appW[(size_t)k * 256 + n];        // emb rows + vis row
    if (k < 568)  return stW[(size_t)(k - 513) * 256 + n]; // bbox + kpts
    return 0.0f;                                           // pad
}

__global__ void build_b_kernel(const float* __restrict__ appW,
                               const float* __restrict__ stW) {
    int chunk = blockIdx.x;   // 0..8
    int n     = threadIdx.x;  // 0..255
#pragma unroll 4
    for (int kp = 0; kp < 32; kp++) {
        int k0 = chunk * 64 + kp * 2;
        float x0 = fetchW(k0, n, appW, stW);
        float x1 = fetchW(k0 + 1, n, appW, stW);
        uint32_t hw, lw;
        split2(x0, x1, hw, lw);
        uint32_t off = SW128((uint32_t)(n * 128 + kp * 4));
        g_Bhi[chunk * 8192 + (off >> 2)] = hw;
        g_Blo[chunk * 8192 + (off >> 2)] = lw;
    }
}

// ---------------- main kernel ----------------
__global__ __launch_bounds__(256, 1)
void seplin_mma(const float* __restrict__ emb,
                const float* __restrict__ vis,
                const float* __restrict__ bbox,
                const float* __restrict__ kpts,
                const int* __restrict__ mask,
                const float* __restrict__ appB,
                const float* __restrict__ stB,
                float* __restrict__ out) {
    extern __shared__ char smem[];
    const uint32_t sb = smem_u32(smem);
    const int tid  = threadIdx.x;
    const int lane = tid & 31;
    const int wid  = tid >> 5;
    const int warpM = wid & 3;    // 4 warps in M (32 rows each)
    const int warpN = wid >> 2;   // 2 warps in N (64 cols each)
    const int rowBase = blockIdx.y * BM;
    const int colBase = blockIdx.x * BN;

    if (tid < 128) {
        reinterpret_cast<float*>(smem + OFF_BIAS)[tid] =
            appB[colBase + tid] + stB[colBase + tid];
        reinterpret_cast<int*>(smem + OFF_MASK)[tid] = mask[rowBase + tid];
    }

    // per-lane ldmatrix address constants
    const uint32_t segBase = (uint32_t)(lane >> 4) * 16;   // 16B segment select
    uint32_t a_row128[2], a_xor[2];
#pragma unroll
    for (int mi = 0; mi < 2; mi++) {
        int r = warpM * 32 + mi * 16 + (lane & 15);
        a_row128[mi] = (uint32_t)r * 128;
        a_xor[mi]    = (uint32_t)(r & 7) << 4;
    }
    uint32_t b_row128[4], b_xor[4];
#pragma unroll
    for (int ng = 0; ng < 4; ng++) {
        int r = warpN * 64 + ng * 16 + (lane & 15);
        b_row128[ng] = (uint32_t)r * 128;
        b_xor[ng]    = (uint32_t)(r & 7) << 4;
    }

    // A-load lane mapping
    const int arow = tid >> 1;          // 0..127
    const int akb  = (tid & 1) * 32;    // k sub-block
    const int arowg = rowBase + arow;

    float acc[2][8][4];
#pragma unroll
    for (int mi = 0; mi < 2; mi++)
#pragma unroll
        for (int ni = 0; ni < 8; ni++)
#pragma unroll
            for (int q = 0; q < 4; q++) acc[mi][ni][q] = 0.0f;

    // ---- loaders ----
    auto loadB = [&](int c, uint32_t stage) {
        const char* srcH = reinterpret_cast<const char*>(g_Bhi) +
                           (size_t)c * 32768 + (size_t)colBase * 128;
        const char* srcL = reinterpret_cast<const char*>(g_Blo) +
                           (size_t)c * 32768 + (size_t)colBase * 128;
        uint32_t dH = sb + stage + ST_BH + tid * 16;
        uint32_t dL = sb + stage + ST_BL + tid * 16;
#pragma unroll
        for (int i = 0; i < 4; i++) {
            cp16(dH + i * 4096, srcH + tid * 16 + i * 4096);
            cp16(dL + i * 4096, srcL + tid * 16 + i * 4096);
        }
    };

    auto loadA = [&](int c, uint32_t stage) {
        float v[32];
        if (c < 8) {
            const float4* s4 = reinterpret_cast<const float4*>(
                emb + (size_t)arowg * 512 + c * 64 + akb);
#pragma unroll
            for (int q = 0; q < 8; q++) {
                float4 f = s4[q];
                v[4 * q + 0] = f.x; v[4 * q + 1] = f.y;
                v[4 * q + 2] = f.z; v[4 * q + 3] = f.w;
            }
        } else {
#pragma unroll
            for (int j = 0; j < 32; j++) {
                int i = akb + j;
                float val = 0.0f;
                if (i == 0)       val = vis[arowg];
                else if (i < 5)   val = bbox[(size_t)arowg * 4 + (i - 1)];
                else if (i < 56)  val = kpts[(size_t)arowg * 51 + (i - 5)];
                v[j] = val;
            }
        }
#pragma unroll
        for (int g = 0; g < 4; g++) {
            uint32_t hw[4], lw[4];
#pragma unroll
            for (int p = 0; p < 4; p++)
                split2(v[8 * g + 2 * p], v[8 * g + 2 * p + 1], hw[p], lw[p]);
            uint32_t off = SW128((uint32_t)(arow * 128 + (akb + 8 * g) * 2));
            *reinterpret_cast<uint4*>(smem + stage + ST_AH + off) =
                make_uint4(hw[0], hw[1], hw[2], hw[3]);
            *reinterpret_cast<uint4*>(smem + stage + ST_AL + off) =
                make_uint4(lw[0], lw[1], lw[2], lw[3]);
        }
    };

    // ---- pipelined mainloop ----
    loadB(0, 0); cp_commit(); loadA(0, 0);

    for (int c = 0; c < NCHUNK; c++) {
        const uint32_t stage = (uint32_t)(c & 1) * STAGE_SZ;
        if (c + 1 < NCHUNK) {
            const uint32_t nstage = (uint32_t)((c + 1) & 1) * STAGE_SZ;
            loadB(c + 1, nstage); cp_commit(); loadA(c + 1, nstage);
            cp_wait<1>();
        } else {
            cp_wait<0>();
        }
        __syncthreads();

        const uint32_t base = sb + stage;
#pragma unroll
        for (int s = 0; s < 4; s++) {
            const uint32_t sseg = segBase + (uint32_t)s * 32;
            uint32_t ah[2][4], al[2][4];
#pragma unroll
            for (int mi = 0; mi < 2; mi++) {
                uint32_t rel = a_row128[mi] + (sseg ^ a_xor[mi]);
                ldsm4(ah[mi], base + ST_AH + rel);
                ldsm4(al[mi], base + ST_AL + rel);
            }
            uint32_t bh[4][4], bl[4][4];
#pragma unroll
            for (int ng = 0; ng < 4; ng++) {
                uint32_t rel = b_row128[ng] + (sseg ^ b_xor[ng]);
                ldsm4(bh[ng], base + ST_BH + rel);
                ldsm4(bl[ng], base + ST_BL + rel);
            }
#pragma unroll
            for (int mi = 0; mi < 2; mi++) {
#pragma unroll
                for (int ng = 0; ng < 4; ng++) {
                    float* d0 = acc[mi][2 * ng];
                    float* d1 = acc[mi][2 * ng + 1];
                    mma16816(d0[0], d0[1], d0[2], d0[3], ah[mi], bh[ng][0], bh[ng][2]);
                    mma16816(d0[0], d0[1], d0[2], d0[3], ah[mi], bl[ng][0], bl[ng][2]);
                    mma16816(d0[0], d0[1], d0[2], d0[3], al[mi], bh[ng][0], bh[ng][2]);
                    mma16816(d1[0], d1[1], d1[2], d1[3], ah[mi], bh[ng][1], bh[ng][3]);
                    mma16816(d1[0], d1[1], d1[2], d1[3], ah[mi], bl[ng][1], bl[ng][3]);
                    mma16816(d1[0], d1[1], d1[2], d1[3], al[mi], bh[ng][1], bh[ng][3]);
                }
            }
        }
        __syncthreads();
    }

    // ---- epilogue: bias + mask + direct store ----
    const float* biasS = reinterpret_cast<const float*>(smem + OFF_BIAS);
    const int*   maskS = reinterpret_cast<const int*>(smem + OFF_MASK);
    const int lr = lane >> 2;         // 0..7
    const int lc = (lane & 3) * 2;    // 0,2,4,6
#pragma unroll
    for (int mi = 0; mi < 2; mi++) {
#pragma unroll
        for (int dh = 0; dh < 2; dh++) {          // row + 0 / +8 (acc regs 0,1 vs 2,3)
            int rloc = warpM * 32 + mi * 16 + lr + dh * 8;
            float mk = maskS[rloc] ? 1.0f : 0.0f;
            float* orow = out + (size_t)(rowBase + rloc) * 256 + colBase;
#pragma unroll
            for (int ni = 0; ni < 8; ni++) {
                int cl = warpN * 64 + ni * 8 + lc;
                float2 w;
                w.x = (acc[mi][ni][2 * dh + 0] + biasS[cl])     * mk;
                w.y = (acc[mi][ni][2 * dh + 1] + biasS[cl + 1]) * mk;
                *reinterpret_cast<float2*>(orow + cl) = w;
            }
        }
    }
}

// ---------------- launch ----------------
extern "C" void kernel_launch(void* const* d_in, const int* in_sizes, int n_in,
                              void* d_out, int out_size) {
    const float* emb  = (const float*)d_in[0];
    const float* vis  = (const float*)d_in[1];
    const float* bbox = (const float*)d_in[2];
    const float* kpts = (const float*)d_in[3];
    const int*   mask = (const int*)d_in[4];
    const float* appW = (const float*)d_in[5];
    const float* appB = (const float*)d_in[6];
    const float* stW  = (const float*)d_in[7];
    const float* stB  = (const float*)d_in[8];

    static int configured = 0;
    if (!configured) {
        cudaFuncSetAttribute(seplin_mma, cudaFuncAttributeMaxDynamicSharedMemorySize,
                             SMEM_TOTAL);
        configured = 1;
    }

    build_b_kernel<<<NCHUNK, 256>>>(appW, stW);
    dim3 grid(256 / BN, GRID_M);   // (2, 2048)
    seplin_mma<<<grid, 256, SMEM_TOTAL>>>(emb, vis, bbox, kpts, mask,
                                          appB, stB, (float*)d_out);
    (void)in_sizes; (void)n_in; (void)out_size;
}

// round 6
// speedup vs baseline: 3.3856x; 2.2510x over previous
#include <cuda_runtime.h>
#include <cstdint>
#include <cstddef>

// ---------------- constants ----------------
static constexpr int BM = 128, BN = 128;
static constexpr int NCHUNK = 9;               // K = 576 (568 + pad) in chunks of 64
static constexpr int MTOT = 262144;
static constexpr int GRID_M = MTOT / BM;       // 2048

// dynamic smem: A 2 stages x 32KB, B 3 stages x 32KB, bias
static constexpr uint32_t A_STAGE_SZ = 32768;   // AH 16KB + AL 16KB
static constexpr uint32_t B_BASE     = 65536;
static constexpr uint32_t B_STAGE_SZ = 32768;   // BH 16KB + BL 16KB
static constexpr uint32_t OFF_BIAS   = 65536 + 3 * 32768;   // 163840
static constexpr uint32_t SMEM_TOTAL = OFF_BIAS + 512;       // 164352

// prepacked swizzled B tile images (hi/lo): [chunk][n=0..255][k=0..63] bf16
__device__ uint32_t g_Bhi[NCHUNK * 8192];
__device__ uint32_t g_Blo[NCHUNK * 8192];

// compaction state
__device__ int g_idx[MTOT];
__device__ int g_blockcnt[256];
__device__ int g_blockoff[256];
__device__ int g_NA;

// ---------------- helpers ----------------
__device__ __forceinline__ uint32_t smem_u32(const void* p) {
    uint32_t a;
    asm("{ .reg .u64 t; cvta.to.shared.u64 t, %1; cvt.u32.u64 %0, t; }"
        : "=r"(a) : "l"(p));
    return a;
}
__device__ __forceinline__ unsigned short f2bf(float x) {
    unsigned short u;
    asm("cvt.rn.bf16.f32 %0, %1;" : "=h"(u) : "f"(x));
    return u;
}
#define SW128(o) ((o) ^ (((o) >> 3) & 0x70))

__device__ __forceinline__ void cp16(uint32_t dst, const void* src) {
    asm volatile("cp.async.cg.shared.global [%0], [%1], 16;"
                 :: "r"(dst), "l"(src) : "memory");
}
__device__ __forceinline__ void cp_commit() {
    asm volatile("cp.async.commit_group;" ::: "memory");
}
template <int N>
__device__ __forceinline__ void cp_wait() {
    asm volatile("cp.async.wait_group %0;" :: "n"(N) : "memory");
}
__device__ __forceinline__ void ldsm4(uint32_t* r, uint32_t a) {
    asm volatile("ldmatrix.sync.aligned.m8n8.x4.shared.b16 {%0,%1,%2,%3}, [%4];"
                 : "=r"(r[0]), "=r"(r[1]), "=r"(r[2]), "=r"(r[3]) : "r"(a));
}
__device__ __forceinline__ void mma16816(float& d0, float& d1, float& d2, float& d3,
                                         const uint32_t* a, uint32_t b0, uint32_t b1) {
    asm volatile(
        "mma.sync.aligned.m16n8k16.row.col.f32.bf16.bf16.f32 "
        "{%0,%1,%2,%3}, {%4,%5,%6,%7}, {%8,%9}, {%0,%1,%2,%3};"
        : "+f"(d0), "+f"(d1), "+f"(d2), "+f"(d3)
        : "r"(a[0]), "r"(a[1]), "r"(a[2]), "r"(a[3]), "r"(b0), "r"(b1));
}
__device__ __forceinline__ void split2(float x0, float x1, uint32_t& hw, uint32_t& lw) {
    uint32_t xb0 = __float_as_uint(x0);
    uint32_t xb1 = __float_as_uint(x1);
    hw = (xb0 >> 16) | (xb1 & 0xFFFF0000u);
    float l0 = x0 - __uint_as_float(xb0 & 0xFFFF0000u);
    float l1 = x1 - __uint_as_float(xb1 & 0xFFFF0000u);
    lw = (uint32_t)f2bf(l0) | ((uint32_t)f2bf(l1) << 16);
}

// ---------------- pre-kernel: pack W hi/lo (swizzled K-major) ----------------
__device__ __forceinline__ float fetchW(int k, int n, const float* appW,
                                        const float* stW) {
    if (k <= 512) return appW[(size_t)k * 256 + n];
    if (k < 568)  return stW[(size_t)(k - 513) * 256 + n];
    return 0.0f;
}

__global__ void build_b_kernel(const float* __restrict__ appW,
                               const float* __restrict__ stW) {
    int chunk = blockIdx.x;
    int n     = threadIdx.x;
#pragma unroll 4
    for (int kp = 0; kp < 32; kp++) {
        int k0 = chunk * 64 + kp * 2;
        uint32_t hw, lw;
        split2(fetchW(k0, n, appW, stW), fetchW(k0 + 1, n, appW, stW), hw, lw);
        uint32_t off = SW128((uint32_t)(n * 128 + kp * 4));
        g_Bhi[chunk * 8192 + (off >> 2)] = hw;
        g_Blo[chunk * 8192 + (off >> 2)] = lw;
    }
}

// ---------------- compaction kernels (deterministic, no atomics) ----------------
__global__ void k_count(const int* __restrict__ mask) {
    __shared__ int s[256];
    int b = blockIdx.x, t = threadIdx.x;
    int r0 = b * 1024 + t * 4;
    int cnt = 0;
#pragma unroll
    for (int i = 0; i < 4; i++) cnt += (mask[r0 + i] != 0);
    s[t] = cnt;
    __syncthreads();
    for (int d = 128; d > 0; d >>= 1) {
        if (t < d) s[t] += s[t + d];
        __syncthreads();
    }
    if (t == 0) g_blockcnt[b] = s[0];
}

__global__ void k_scan() {
    __shared__ int s[256];
    int t = threadIdx.x;
    int my = g_blockcnt[t];
    s[t] = my;
    __syncthreads();
    for (int d = 1; d < 256; d <<= 1) {
        int add = (t >= d) ? s[t - d] : 0;
        __syncthreads();
        s[t] += add;
        __syncthreads();
    }
    g_blockoff[t] = s[t] - my;           // exclusive
    if (t == 255) g_NA = s[255];
}

__global__ void k_scatter(const int* __restrict__ mask) {
    __shared__ int s[256];
    int b = blockIdx.x, t = threadIdx.x;
    int r0 = b * 1024 + t * 4;
    int m[4], cnt = 0;
#pragma unroll
    for (int i = 0; i < 4; i++) { m[i] = (mask[r0 + i] != 0); cnt += m[i]; }
    s[t] = cnt;
    __syncthreads();
    for (int d = 1; d < 256; d <<= 1) {
        int add = (t >= d) ? s[t - d] : 0;
        __syncthreads();
        s[t] += add;
        __syncthreads();
    }
    int off = g_blockoff[b] + s[t] - cnt;
#pragma unroll
    for (int i = 0; i < 4; i++)
        if (m[i]) g_idx[off++] = r0 + i;
}

__global__ void k_zero(const int* __restrict__ mask, float4* __restrict__ out4) {
    int gid = blockIdx.x * 256 + threadIdx.x;   // 16384*256 = 262144*16
    int row = gid >> 4, seg = gid & 15;
    if (mask[row] == 0)
        out4[(size_t)row * 16 + seg] = make_float4(0.f, 0.f, 0.f, 0.f);
}

// ---------------- main kernel ----------------
__global__ __launch_bounds__(256, 1)
void seplin_mma(const float* __restrict__ emb,
                const float* __restrict__ vis,
                const float* __restrict__ bbox,
                const float* __restrict__ kpts,
                const float* __restrict__ appB,
                const float* __restrict__ stB,
                float* __restrict__ out) {
    const int na = g_NA;
    const int rowBase = blockIdx.y * BM;      // index into compacted rows
    if (rowBase >= na) return;

    extern __shared__ char smem[];
    const uint32_t sb = smem_u32(smem);
    const int tid  = threadIdx.x;
    const int lane = tid & 31;
    const int wid  = tid >> 5;
    const int warpM = wid & 3;
    const int warpN = wid >> 2;
    const int colBase = blockIdx.x * BN;

    if (tid < 128)
        reinterpret_cast<float*>(smem + OFF_BIAS)[tid] =
            appB[colBase + tid] + stB[colBase + tid];

    // ldmatrix per-lane constants
    const uint32_t segBase = (uint32_t)(lane >> 4) * 16;
    uint32_t a_row128[2], a_xor[2];
#pragma unroll
    for (int mi = 0; mi < 2; mi++) {
        int r = warpM * 32 + mi * 16 + (lane & 15);
        a_row128[mi] = (uint32_t)r * 128;
        a_xor[mi]    = (uint32_t)(r & 7) << 4;
    }
    uint32_t b_row128[4], b_xor[4];
#pragma unroll
    for (int ng = 0; ng < 4; ng++) {
        int r = warpN * 64 + ng * 16 + (lane & 15);
        b_row128[ng] = (uint32_t)r * 128;
        b_xor[ng]    = (uint32_t)(r & 7) << 4;
    }

    // A-load mapping: thread -> (compacted row, k half)
    const int arow = tid >> 1;
    const int akb  = (tid & 1) * 32;
    const int agr  = rowBase + arow;
    const int asrc = (agr < na) ? g_idx[agr] : 0;

    float acc[2][8][4];
#pragma unroll
    for (int mi = 0; mi < 2; mi++)
#pragma unroll
        for (int ni = 0; ni < 8; ni++)
#pragma unroll
            for (int q = 0; q < 4; q++) acc[mi][ni][q] = 0.0f;

    float v[32];   // pipelined A registers (holds chunk c+1 during iter c)

    auto loadB = [&](int c, uint32_t bst) {
        const char* srcH = reinterpret_cast<const char*>(g_Bhi) +
                           (size_t)c * 32768 + (size_t)colBase * 128;
        const char* srcL = reinterpret_cast<const char*>(g_Blo) +
                           (size_t)c * 32768 + (size_t)colBase * 128;
        uint32_t dH = sb + bst + tid * 16;
        uint32_t dL = sb + bst + 16384 + tid * 16;
#pragma unroll
        for (int i = 0; i < 4; i++) {
            cp16(dH + i * 4096, srcH + tid * 16 + i * 4096);
            cp16(dL + i * 4096, srcL + tid * 16 + i * 4096);
        }
    };
    auto ldgA = [&](int c) {
        if (c < 8) {
            const float4* s4 = reinterpret_cast<const float4*>(
                emb + (size_t)asrc * 512 + c * 64 + akb);
#pragma unroll
            for (int q = 0; q < 8; q++) {
                float4 f = s4[q];
                v[4 * q + 0] = f.x; v[4 * q + 1] = f.y;
                v[4 * q + 2] = f.z; v[4 * q + 3] = f.w;
            }
        } else {
#pragma unroll
            for (int j = 0; j < 32; j++) {
                int i = akb + j;
                float val = 0.0f;
                if (i == 0)       val = vis[asrc];
                else if (i < 5)   val = bbox[(size_t)asrc * 4 + (i - 1)];
                else if (i < 56)  val = kpts[(size_t)asrc * 51 + (i - 5)];
                v[j] = val;
            }
        }
    };
    auto stsA = [&](uint32_t ast) {
#pragma unroll
        for (int g = 0; g < 4; g++) {
            uint32_t hw[4], lw[4];
#pragma unroll
            for (int p = 0; p < 4; p++)
                split2(v[8 * g + 2 * p], v[8 * g + 2 * p + 1], hw[p], lw[p]);
            uint32_t off = SW128((uint32_t)(arow * 128 + (akb + 8 * g) * 2));
            *reinterpret_cast<uint4*>(smem + ast + off) =
                make_uint4(hw[0], hw[1], hw[2], hw[3]);
            *reinterpret_cast<uint4*>(smem + ast + 16384 + off) =
                make_uint4(lw[0], lw[1], lw[2], lw[3]);
        }
    };

    // ---- prologue ----
    loadB(0, B_BASE); cp_commit();
    loadB(1, B_BASE + B_STAGE_SZ); cp_commit();
    ldgA(0);
    stsA(0);                 // one-time exposed DRAM latency
    ldgA(1);

    // ---- mainloop ----
    for (int c = 0; c < NCHUNK; c++) {
        const uint32_t aSt = (uint32_t)(c & 1) * A_STAGE_SZ;
        const uint32_t bSt = B_BASE + (uint32_t)(c % 3) * B_STAGE_SZ;

        cp_wait<1>();            // B(c) resident (B(c+1) may be in flight)
        __syncthreads();         // A(c) STS visible to all
        if (c + 2 < NCHUNK) loadB(c + 2, B_BASE + (uint32_t)((c + 2) % 3) * B_STAGE_SZ);
        cp_commit();

        const uint32_t baseA = sb + aSt;
        const uint32_t baseB = sb + bSt;
#pragma unroll
        for (int s = 0; s < 4; s++) {
            const uint32_t sseg = segBase + (uint32_t)s * 32;
            uint32_t ah[2][4], al[2][4];
#pragma unroll
            for (int mi = 0; mi < 2; mi++) {
                uint32_t rel = a_row128[mi] + (sseg ^ a_xor[mi]);
                ldsm4(ah[mi], baseA + rel);
                ldsm4(al[mi], baseA + 16384 + rel);
            }
            uint32_t bh[4][4], bl[4][4];
#pragma unroll
            for (int ng = 0; ng < 4; ng++) {
                uint32_t rel = b_row128[ng] + (sseg ^ b_xor[ng]);
                ldsm4(bh[ng], baseB + rel);
                ldsm4(bl[ng], baseB + 16384 + rel);
            }
#pragma unroll
            for (int mi = 0; mi < 2; mi++) {
#pragma unroll
                for (int ng = 0; ng < 4; ng++) {
                    float* d0 = acc[mi][2 * ng];
                    float* d1 = acc[mi][2 * ng + 1];
                    mma16816(d0[0], d0[1], d0[2], d0[3], ah[mi], bh[ng][0], bh[ng][2]);
                    mma16816(d0[0], d0[1], d0[2], d0[3], ah[mi], bl[ng][0], bl[ng][2]);
                    mma16816(d0[0], d0[1], d0[2], d0[3], al[mi], bh[ng][0], bh[ng][2]);
                    mma16816(d1[0], d1[1], d1[2], d1[3], ah[mi], bh[ng][1], bh[ng][3]);
                    mma16816(d1[0], d1[1], d1[2], d1[3], ah[mi], bl[ng][1], bl[ng][3]);
                    mma16816(d1[0], d1[1], d1[2], d1[3], al[mi], bh[ng][1], bh[ng][3]);
                }
            }
        }

        // feed the pipeline: STS A(c+1) from regs, then refill regs with A(c+2)
        if (c + 1 < NCHUNK) {
            stsA((uint32_t)((c + 1) & 1) * A_STAGE_SZ);
            if (c + 2 < NCHUNK) ldgA(c + 2);
        }
    }

    // ---- epilogue: bias + compacted scatter store ----
    const float* biasS = reinterpret_cast<const float*>(smem + OFF_BIAS);
    const int lr = lane >> 2;
    const int lc = (lane & 3) * 2;
#pragma unroll
    for (int mi = 0; mi < 2; mi++) {
#pragma unroll
        for (int dh = 0; dh < 2; dh++) {
            int rloc = warpM * 32 + mi * 16 + lr + dh * 8;
            int gr = rowBase + rloc;
            if (gr < na) {
                int realrow = g_idx[gr];
                float* orow = out + (size_t)realrow * 256 + colBase;
#pragma unroll
                for (int ni = 0; ni < 8; ni++) {
                    int cl = warpN * 64 + ni * 8 + lc;
                    float2 w;
                    w.x = acc[mi][ni][2 * dh + 0] + biasS[cl];
                    w.y = acc[mi][ni][2 * dh + 1] + biasS[cl + 1];
                    *reinterpret_cast<float2*>(orow + cl) = w;
                }
            }
        }
    }
}

// ---------------- launch ----------------
extern "C" void kernel_launch(void* const* d_in, const int* in_sizes, int n_in,
                              void* d_out, int out_size) {
    const float* emb  = (const float*)d_in[0];
    const float* vis  = (const float*)d_in[1];
    const float* bbox = (const float*)d_in[2];
    const float* kpts = (const float*)d_in[3];
    const int*   mask = (const int*)d_in[4];
    const float* appW = (const float*)d_in[5];
    const float* appB = (const float*)d_in[6];
    const float* stW  = (const float*)d_in[7];
    const float* stB  = (const float*)d_in[8];

    static int configured = 0;
    if (!configured) {
        cudaFuncSetAttribute(seplin_mma, cudaFuncAttributeMaxDynamicSharedMemorySize,
                             SMEM_TOTAL);
        configured = 1;
    }

    build_b_kernel<<<NCHUNK, 256>>>(appW, stW);
    k_count<<<256, 256>>>(mask);
    k_scan<<<1, 256>>>();
    k_scatter<<<256, 256>>>(mask);
    k_zero<<<16384, 256>>>(mask, (float4*)d_out);

    dim3 grid(256 / BN, GRID_M);   // (2, 2048); CTAs past NA exit early
    seplin_mma<<<grid, 256, SMEM_TOTAL>>>(emb, vis, bbox, kpts,
                                          appB, stB, (float*)d_out);
    (void)in_sizes; (void)n_in; (void)out_size;
}

// round 7
// speedup vs baseline: 3.7070x; 1.0949x over previous
#include <cuda_runtime.h>
#include <cstdint>
#include <cstddef>

// ---------------- constants ----------------
static constexpr int BM = 128;                 // M rows per CTA
static constexpr int NCHUNK = 9;               // K = 576 (568 + pad) in chunks of 64
static constexpr int MTOT = 262144;
static constexpr int GRID_M = MTOT / BM;       // 2048

// dynamic smem: A 2 stages x 32KB, B 2 stages x 64KB, bias
static constexpr uint32_t A_STAGE_SZ = 32768;   // AH 16KB + AL 16KB
static constexpr uint32_t B_BASE     = 65536;
static constexpr uint32_t B_STAGE_SZ = 65536;   // BH 32KB + BL 32KB
static constexpr uint32_t OFF_BIAS   = B_BASE + 2 * B_STAGE_SZ;   // 196608
static constexpr uint32_t SMEM_TOTAL = OFF_BIAS + 1024;           // 197632

// prepacked swizzled B images (hi/lo): [chunk][n=0..255][k=0..63] bf16
__device__ uint32_t g_Bhi[NCHUNK * 8192];
__device__ uint32_t g_Blo[NCHUNK * 8192];

// compaction state (two-sided: actives from front, inactives from back)
__device__ int g_idx[MTOT];
__device__ int g_blockcnt[256];
__device__ int g_blockoff[256];
__device__ int g_NA;

// ---------------- helpers ----------------
__device__ __forceinline__ uint32_t smem_u32(const void* p) {
    uint32_t a;
    asm("{ .reg .u64 t; cvta.to.shared.u64 t, %1; cvt.u32.u64 %0, t; }"
        : "=r"(a) : "l"(p));
    return a;
}
__device__ __forceinline__ unsigned short f2bf(float x) {
    unsigned short u;
    asm("cvt.rn.bf16.f32 %0, %1;" : "=h"(u) : "f"(x));
    return u;
}
#define SW128(o) ((o) ^ (((o) >> 3) & 0x70))

__device__ __forceinline__ void cp16(uint32_t dst, const void* src) {
    asm volatile("cp.async.cg.shared.global [%0], [%1], 16;"
                 :: "r"(dst), "l"(src) : "memory");
}
__device__ __forceinline__ void cp_commit() {
    asm volatile("cp.async.commit_group;" ::: "memory");
}
template <int N>
__device__ __forceinline__ void cp_wait() {
    asm volatile("cp.async.wait_group %0;" :: "n"(N) : "memory");
}
__device__ __forceinline__ void ldsm4(uint32_t* r, uint32_t a) {
    asm volatile("ldmatrix.sync.aligned.m8n8.x4.shared.b16 {%0,%1,%2,%3}, [%4];"
                 : "=r"(r[0]), "=r"(r[1]), "=r"(r[2]), "=r"(r[3]) : "r"(a));
}
__device__ __forceinline__ void mma16816(float& d0, float& d1, float& d2, float& d3,
                                         const uint32_t* a, uint32_t b0, uint32_t b1) {
    asm volatile(
        "mma.sync.aligned.m16n8k16.row.col.f32.bf16.bf16.f32 "
        "{%0,%1,%2,%3}, {%4,%5,%6,%7}, {%8,%9}, {%0,%1,%2,%3};"
        : "+f"(d0), "+f"(d1), "+f"(d2), "+f"(d3)
        : "r"(a[0]), "r"(a[1]), "r"(a[2]), "r"(a[3]), "r"(b0), "r"(b1));
}
__device__ __forceinline__ void split2(float x0, float x1, uint32_t& hw, uint32_t& lw) {
    uint32_t xb0 = __float_as_uint(x0);
    uint32_t xb1 = __float_as_uint(x1);
    hw = (xb0 >> 16) | (xb1 & 0xFFFF0000u);
    float l0 = x0 - __uint_as_float(xb0 & 0xFFFF0000u);
    float l1 = x1 - __uint_as_float(xb1 & 0xFFFF0000u);
    lw = (uint32_t)f2bf(l0) | ((uint32_t)f2bf(l1) << 16);
}

// ---------------- pre-kernel: pack W hi/lo (swizzled K-major) ----------------
__device__ __forceinline__ float fetchW(int k, int n, const float* appW,
                                        const float* stW) {
    if (k <= 512) return appW[(size_t)k * 256 + n];
    if (k < 568)  return stW[(size_t)(k - 513) * 256 + n];
    return 0.0f;
}

__global__ void build_b_kernel(const float* __restrict__ appW,
                               const float* __restrict__ stW) {
    int chunk = blockIdx.x;
    int n     = threadIdx.x;
#pragma unroll 4
    for (int kp = 0; kp < 32; kp++) {
        int k0 = chunk * 64 + kp * 2;
        uint32_t hw, lw;
        split2(fetchW(k0, n, appW, stW), fetchW(k0 + 1, n, appW, stW), hw, lw);
        uint32_t off = SW128((uint32_t)(n * 128 + kp * 4));
        g_Bhi[chunk * 8192 + (off >> 2)] = hw;
        g_Blo[chunk * 8192 + (off >> 2)] = lw;
    }
}

// ---------------- compaction (deterministic, no atomics) ----------------
__global__ void k_count(const int* __restrict__ mask) {
    __shared__ int s[256];
    int b = blockIdx.x, t = threadIdx.x;
    int r0 = b * 1024 + t * 4;
    int cnt = 0;
#pragma unroll
    for (int i = 0; i < 4; i++) cnt += (mask[r0 + i] != 0);
    s[t] = cnt;
    __syncthreads();
    for (int d = 128; d > 0; d >>= 1) {
        if (t < d) s[t] += s[t + d];
        __syncthreads();
    }
    if (t == 0) g_blockcnt[b] = s[0];
}

__global__ void k_scan() {
    __shared__ int s[256];
    int t = threadIdx.x;
    int my = g_blockcnt[t];
    s[t] = my;
    __syncthreads();
    for (int d = 1; d < 256; d <<= 1) {
        int add = (t >= d) ? s[t - d] : 0;
        __syncthreads();
        s[t] += add;
        __syncthreads();
    }
    g_blockoff[t] = s[t] - my;           // exclusive
    if (t == 255) g_NA = s[255];
}

__global__ void k_scatter(const int* __restrict__ mask) {
    __shared__ int s[256];
    int b = blockIdx.x, t = threadIdx.x;
    int r0 = b * 1024 + t * 4;
    int m[4], cnt = 0;
#pragma unroll
    for (int i = 0; i < 4; i++) { m[i] = (mask[r0 + i] != 0); cnt += m[i]; }
    s[t] = cnt;
    __syncthreads();
    for (int d = 1; d < 256; d <<= 1) {
        int add = (t >= d) ? s[t - d] : 0;
        __syncthreads();
        s[t] += add;
        __syncthreads();
    }
    int act_excl = g_blockoff[b] + s[t] - cnt;   // actives before r0
#pragma unroll
    for (int i = 0; i < 4; i++) {
        int r = r0 + i;
        if (m[i]) {
            g_idx[act_excl] = r;
            act_excl++;
        } else {
            int inact_excl = r - act_excl;       // inactives before r
            g_idx[MTOT - 1 - inact_excl] = r;
        }
    }
}

// ---------------- main kernel ----------------
__global__ __launch_bounds__(256, 1)
void seplin_mma(const float* __restrict__ emb,
                const float* __restrict__ vis,
                const float* __restrict__ bbox,
                const float* __restrict__ kpts,
                const float* __restrict__ appB,
                const float* __restrict__ stB,
                float* __restrict__ out) {
    const int na = g_NA;
    const int rowBase = blockIdx.x * BM;      // index into permuted rows
    const int tid  = threadIdx.x;

    // ---- pure-zero CTA: all its rows are inactive ----
    if (rowBase >= na) {
        int j   = tid >> 1;                   // 0..127
        int seg = tid & 1;                    // half-row
        int realrow = g_idx[rowBase + j];
        float4* o4 = reinterpret_cast<float4*>(out + (size_t)realrow * 256 + seg * 128);
        float4 z = make_float4(0.f, 0.f, 0.f, 0.f);
#pragma unroll
        for (int i = 0; i < 32; i++) o4[i] = z;
        return;
    }

    extern __shared__ char smem[];
    const uint32_t sb = smem_u32(smem);
    const int lane = tid & 31;
    const int wid  = tid >> 5;
    const int warpM = wid >> 2;   // 0..1  (64 rows each)
    const int warpN = wid & 3;    // 0..3  (64 cols each)

    reinterpret_cast<float*>(smem + OFF_BIAS)[tid] = appB[tid] + stB[tid];

    // ldmatrix per-lane constants
    const uint32_t segBase = (uint32_t)(lane >> 4) * 16;
    uint32_t a_row128[4], a_xor[4];
#pragma unroll
    for (int mi = 0; mi < 4; mi++) {
        int r = warpM * 64 + mi * 16 + (lane & 15);
        a_row128[mi] = (uint32_t)r * 128;
        a_xor[mi]    = (uint32_t)(r & 7) << 4;
    }
    uint32_t b_row128[4], b_xor[4];
#pragma unroll
    for (int ng = 0; ng < 4; ng++) {
        int r = warpN * 64 + ng * 16 + (lane & 15);
        b_row128[ng] = (uint32_t)r * 128;
        b_xor[ng]    = (uint32_t)(r & 7) << 4;
    }

    // A-load mapping: thread -> (permuted row, k half)
    const int arow = tid >> 1;
    const int akb  = (tid & 1) * 32;
    const int asrc = g_idx[rowBase + arow];   // boundary CTA: inactive rows load real data; discarded

    float acc[4][8][4];
#pragma unroll
    for (int mi = 0; mi < 4; mi++)
#pragma unroll
        for (int ni = 0; ni < 8; ni++)
#pragma unroll
            for (int q = 0; q < 4; q++) acc[mi][ni][q] = 0.0f;

    float v[32];   // A pipeline regs (holds chunk c+1 during iter c tail)

    auto loadB = [&](int c, uint32_t bst) {
        const char* srcH = reinterpret_cast<const char*>(g_Bhi) + (size_t)c * 32768;
        const char* srcL = reinterpret_cast<const char*>(g_Blo) + (size_t)c * 32768;
        uint32_t dH = sb + bst + tid * 16;
        uint32_t dL = sb + bst + 32768 + tid * 16;
#pragma unroll
        for (int i = 0; i < 8; i++) {
            cp16(dH + i * 4096, srcH + tid * 16 + i * 4096);
            cp16(dL + i * 4096, srcL + tid * 16 + i * 4096);
        }
    };
    auto ldgA = [&](int c) {
        if (c < 8) {
            const float4* s4 = reinterpret_cast<const float4*>(
                emb + (size_t)asrc * 512 + c * 64 + akb);
#pragma unroll
            for (int q = 0; q < 8; q++) {
                float4 f = s4[q];
                v[4 * q + 0] = f.x; v[4 * q + 1] = f.y;
                v[4 * q + 2] = f.z; v[4 * q + 3] = f.w;
            }
        } else {
#pragma unroll
            for (int j = 0; j < 32; j++) {
                int i = akb + j;
                float val = 0.0f;
                if (i == 0)       val = vis[asrc];
                else if (i < 5)   val = bbox[(size_t)asrc * 4 + (i - 1)];
                else if (i < 56)  val = kpts[(size_t)asrc * 51 + (i - 5)];
                v[j] = val;
            }
        }
    };
    auto stsA = [&](uint32_t ast) {
#pragma unroll
        for (int g = 0; g < 4; g++) {
            uint32_t hw[4], lw[4];
#pragma unroll
            for (int p = 0; p < 4; p++)
                split2(v[8 * g + 2 * p], v[8 * g + 2 * p + 1], hw[p], lw[p]);
            uint32_t off = SW128((uint32_t)(arow * 128 + (akb + 8 * g) * 2));
            *reinterpret_cast<uint4*>(smem + ast + off) =
                make_uint4(hw[0], hw[1], hw[2], hw[3]);
            *reinterpret_cast<uint4*>(smem + ast + 16384 + off) =
                make_uint4(lw[0], lw[1], lw[2], lw[3]);
        }
    };

    // ---- prologue ----
    loadB(0, B_BASE); cp_commit();
    ldgA(0);
    stsA(0);                 // one-time exposed latency
    ldgA(1);

    // ---- mainloop ----
    for (int c = 0; c < NCHUNK; c++) {
        const uint32_t aSt = (uint32_t)(c & 1) * A_STAGE_SZ;
        const uint32_t bSt = B_BASE + (uint32_t)(c & 1) * B_STAGE_SZ;

        cp_wait<0>();            // B(c) resident
        __syncthreads();         // A(c) visible; all warps done with stage buffers of c-1
        if (c + 1 < NCHUNK)
            loadB(c + 1, B_BASE + (uint32_t)((c + 1) & 1) * B_STAGE_SZ);
        cp_commit();

        const uint32_t baseA = sb + aSt;
        const uint32_t baseB = sb + bSt;
#pragma unroll
        for (int s = 0; s < 4; s++) {
            const uint32_t sseg = segBase + (uint32_t)s * 32;
            uint32_t bh[4][4], bl[4][4];
#pragma unroll
            for (int ng = 0; ng < 4; ng++) {
                uint32_t rel = b_row128[ng] + (sseg ^ b_xor[ng]);
                ldsm4(bh[ng], baseB + rel);
                ldsm4(bl[ng], baseB + 32768 + rel);
            }
#pragma unroll
            for (int mi = 0; mi < 4; mi++) {
                uint32_t ah[4], al[4];
                uint32_t rel = a_row128[mi] + (sseg ^ a_xor[mi]);
                ldsm4(ah, baseA + rel);
                ldsm4(al, baseA + 16384 + rel);
#pragma unroll
                for (int ng = 0; ng < 4; ng++) {
                    float* d0 = acc[mi][2 * ng];
                    float* d1 = acc[mi][2 * ng + 1];
                    mma16816(d0[0], d0[1], d0[2], d0[3], ah, bh[ng][0], bh[ng][2]);
                    mma16816(d0[0], d0[1], d0[2], d0[3], ah, bl[ng][0], bl[ng][2]);
                    mma16816(d0[0], d0[1], d0[2], d0[3], al, bh[ng][0], bh[ng][2]);
                    mma16816(d1[0], d1[1], d1[2], d1[3], ah, bh[ng][1], bh[ng][3]);
                    mma16816(d1[0], d1[1], d1[2], d1[3], ah, bl[ng][1], bl[ng][3]);
                    mma16816(d1[0], d1[1], d1[2], d1[3], al, bh[ng][1], bh[ng][3]);
                }
            }
        }

        // feed pipeline: STS A(c+1) from regs, refill regs with A(c+2)
        if (c + 1 < NCHUNK) {
            stsA((uint32_t)((c + 1) & 1) * A_STAGE_SZ);
            if (c + 2 < NCHUNK) ldgA(c + 2);
        }
    }

    // ---- epilogue: bias + permuted scatter store (zeros for inactive rows) ----
    const float* biasS = reinterpret_cast<const float*>(smem + OFF_BIAS);
    const int lr = lane >> 2;
    const int lc = (lane & 3) * 2;
#pragma unroll
    for (int mi = 0; mi < 4; mi++) {
#pragma unroll
        for (int dh = 0; dh < 2; dh++) {
            int rloc = warpM * 64 + mi * 16 + lr + dh * 8;
            int gr = rowBase + rloc;
            int realrow = g_idx[gr];
            float* orow = out + (size_t)realrow * 256;
            if (gr < na) {
#pragma unroll
                for (int ni = 0; ni < 8; ni++) {
                    int cl = warpN * 64 + ni * 8 + lc;
                    float2 w;
                    w.x = acc[mi][ni][2 * dh + 0] + biasS[cl];
                    w.y = acc[mi][ni][2 * dh + 1] + biasS[cl + 1];
                    *reinterpret_cast<float2*>(orow + cl) = w;
                }
            } else {
#pragma unroll
                for (int ni = 0; ni < 8; ni++) {
                    int cl = warpN * 64 + ni * 8 + lc;
                    *reinterpret_cast<float2*>(orow + cl) = make_float2(0.f, 0.f);
                }
            }
        }
    }
}

// ---------------- launch ----------------
extern "C" void kernel_launch(void* const* d_in, const int* in_sizes, int n_in,
                              void* d_out, int out_size) {
    const float* emb  = (const float*)d_in[0];
    const float* vis  = (const float*)d_in[1];
    const float* bbox = (const float*)d_in[2];
    const float* kpts = (const float*)d_in[3];
    const int*   mask = (const int*)d_in[4];
    const float* appW = (const float*)d_in[5];
    const float* appB = (const float*)d_in[6];
    const float* stW  = (const float*)d_in[7];
    const float* stB  = (const float*)d_in[8];

    static int configured = 0;
    if (!configured) {
        cudaFuncSetAttribute(seplin_mma, cudaFuncAttributeMaxDynamicSharedMemorySize,
                             SMEM_TOTAL);
        configured = 1;
    }

    build_b_kernel<<<NCHUNK, 256>>>(appW, stW);
    k_count<<<256, 256>>>(mask);
    k_scan<<<1, 256>>>();
    k_scatter<<<256, 256>>>(mask);

    seplin_mma<<<GRID_M, 256, SMEM_TOTAL>>>(emb, vis, bbox, kpts,
                                            appB, stB, (float*)d_out);
    (void)in_sizes; (void)n_in; (void)out_size;
}

// round 8
// speedup vs baseline: 3.8647x; 1.0425x over previous
#include <cuda_runtime.h>
#include <cstdint>
#include <cstddef>

// ---------------- constants ----------------
static constexpr int BM = 128;                 // M rows per CTA
static constexpr int NCHUNK = 9;               // K = 576 (568 + pad) in chunks of 64
static constexpr int MTOT = 262144;
static constexpr int GRID_M = MTOT / BM;       // 2048
static constexpr int NTHR = 512;

// dynamic smem: A 2 stages x 32KB, B 2 stages x 64KB, bias
static constexpr uint32_t A_STAGE_SZ = 32768;   // AH 16KB + AL 16KB
static constexpr uint32_t B_BASE     = 65536;
static constexpr uint32_t B_STAGE_SZ = 65536;   // BH 32KB + BL 32KB
static constexpr uint32_t OFF_BIAS   = B_BASE + 2 * B_STAGE_SZ;   // 196608
static constexpr uint32_t SMEM_TOTAL = OFF_BIAS + 1024;           // 197632

// prepacked swizzled B images (hi/lo): [chunk][n=0..255][k=0..63] bf16
__device__ uint32_t g_Bhi[NCHUNK * 8192];
__device__ uint32_t g_Blo[NCHUNK * 8192];

// compaction state (two-sided: actives from front, inactives from back)
__device__ int g_idx[MTOT];
__device__ int g_blockcnt[256];
__device__ int g_NA;

// ---------------- helpers ----------------
__device__ __forceinline__ uint32_t smem_u32(const void* p) {
    uint32_t a;
    asm("{ .reg .u64 t; cvta.to.shared.u64 t, %1; cvt.u32.u64 %0, t; }"
        : "=r"(a) : "l"(p));
    return a;
}
__device__ __forceinline__ unsigned short f2bf(float x) {
    unsigned short u;
    asm("cvt.rn.bf16.f32 %0, %1;" : "=h"(u) : "f"(x));
    return u;
}
#define SW128(o) ((o) ^ (((o) >> 3) & 0x70))

__device__ __forceinline__ void cp16(uint32_t dst, const void* src) {
    asm volatile("cp.async.cg.shared.global [%0], [%1], 16;"
                 :: "r"(dst), "l"(src) : "memory");
}
__device__ __forceinline__ void cp_commit() {
    asm volatile("cp.async.commit_group;" ::: "memory");
}
template <int N>
__device__ __forceinline__ void cp_wait() {
    asm volatile("cp.async.wait_group %0;" :: "n"(N) : "memory");
}
__device__ __forceinline__ void ldsm4(uint32_t* r, uint32_t a) {
    asm volatile("ldmatrix.sync.aligned.m8n8.x4.shared.b16 {%0,%1,%2,%3}, [%4];"
                 : "=r"(r[0]), "=r"(r[1]), "=r"(r[2]), "=r"(r[3]) : "r"(a));
}
__device__ __forceinline__ void mma16816(float& d0, float& d1, float& d2, float& d3,
                                         const uint32_t* a, uint32_t b0, uint32_t b1) {
    asm volatile(
        "mma.sync.aligned.m16n8k16.row.col.f32.bf16.bf16.f32 "
        "{%0,%1,%2,%3}, {%4,%5,%6,%7}, {%8,%9}, {%0,%1,%2,%3};"
        : "+f"(d0), "+f"(d1), "+f"(d2), "+f"(d3)
        : "r"(a[0]), "r"(a[1]), "r"(a[2]), "r"(a[3]), "r"(b0), "r"(b1));
}
__device__ __forceinline__ void split2(float x0, float x1, uint32_t& hw, uint32_t& lw) {
    uint32_t xb0 = __float_as_uint(x0);
    uint32_t xb1 = __float_as_uint(x1);
    hw = (xb0 >> 16) | (xb1 & 0xFFFF0000u);
    float l0 = x0 - __uint_as_float(xb0 & 0xFFFF0000u);
    float l1 = x1 - __uint_as_float(xb1 & 0xFFFF0000u);
    lw = (uint32_t)f2bf(l0) | ((uint32_t)f2bf(l1) << 16);
}

// ---------------- prep1: pack W (blocks 0..8) + mask count (blocks 9..264) ----------------
__device__ __forceinline__ float fetchW(int k, int n, const float* appW,
                                        const float* stW) {
    if (k <= 512) return appW[(size_t)k * 256 + n];
    if (k < 568)  return stW[(size_t)(k - 513) * 256 + n];
    return 0.0f;
}

__global__ void k_prep1(const float* __restrict__ appW,
                        const float* __restrict__ stW,
                        const int* __restrict__ mask) {
    int t = threadIdx.x;
    if (blockIdx.x < NCHUNK) {
        int chunk = blockIdx.x;
        int n = t;
#pragma unroll 4
        for (int kp = 0; kp < 32; kp++) {
            int k0 = chunk * 64 + kp * 2;
            uint32_t hw, lw;
            split2(fetchW(k0, n, appW, stW), fetchW(k0 + 1, n, appW, stW), hw, lw);
            uint32_t off = SW128((uint32_t)(n * 128 + kp * 4));
            g_Bhi[chunk * 8192 + (off >> 2)] = hw;
            g_Blo[chunk * 8192 + (off >> 2)] = lw;
        }
    } else {
        __shared__ int s[256];
        int b = blockIdx.x - NCHUNK;
        int r0 = b * 1024 + t * 4;
        int cnt = 0;
#pragma unroll
        for (int i = 0; i < 4; i++) cnt += (mask[r0 + i] != 0);
        s[t] = cnt;
        __syncthreads();
        for (int d = 128; d > 0; d >>= 1) {
            if (t < d) s[t] += s[t + d];
            __syncthreads();
        }
        if (t == 0) g_blockcnt[b] = s[0];
    }
}

// ---------------- prep2: inline scan of block counts + two-sided scatter ----------------
__global__ void k_prep2(const int* __restrict__ mask) {
    __shared__ int sc[256];
    __shared__ int s[256];
    __shared__ int blockoff;
    int b = blockIdx.x, t = threadIdx.x;

    // scan all 256 block counts locally
    int cv = g_blockcnt[t];
    sc[t] = cv;
    __syncthreads();
    for (int d = 1; d < 256; d <<= 1) {
        int add = (t >= d) ? sc[t - d] : 0;
        __syncthreads();
        sc[t] += add;
        __syncthreads();
    }
    if (t == b) blockoff = sc[b] - cv;          // exclusive offset of this block
    if (t == 255) g_NA = sc[255];               // every block writes same value
    __syncthreads();

    // per-block scan of local mask
    int r0 = b * 1024 + t * 4;
    int m[4], cnt = 0;
#pragma unroll
    for (int i = 0; i < 4; i++) { m[i] = (mask[r0 + i] != 0); cnt += m[i]; }
    s[t] = cnt;
    __syncthreads();
    for (int d = 1; d < 256; d <<= 1) {
        int add = (t >= d) ? s[t - d] : 0;
        __syncthreads();
        s[t] += add;
        __syncthreads();
    }
    int act_excl = blockoff + s[t] - cnt;       // actives before r0
#pragma unroll
    for (int i = 0; i < 4; i++) {
        int r = r0 + i;
        if (m[i]) {
            g_idx[act_excl] = r;
            act_excl++;
        } else {
            int inact_excl = r - act_excl;      // inactives before r
            g_idx[MTOT - 1 - inact_excl] = r;
        }
    }
}

// ---------------- main kernel ----------------
__global__ __launch_bounds__(NTHR, 1)
void seplin_mma(const float* __restrict__ emb,
                const float* __restrict__ vis,
                const float* __restrict__ bbox,
                const float* __restrict__ kpts,
                const float* __restrict__ appB,
                const float* __restrict__ stB,
                float* __restrict__ out) {
    const int na = g_NA;
    const int rowBase = blockIdx.x * BM;      // index into permuted rows
    const int tid  = threadIdx.x;

    // ---- pure-zero CTA: all its rows are inactive ----
    if (rowBase >= na) {
        int j   = tid >> 2;                   // 0..127
        int seg = tid & 3;                    // quarter-row
        int realrow = g_idx[rowBase + j];
        float4* o4 = reinterpret_cast<float4*>(out + (size_t)realrow * 256) + seg * 16;
        float4 z = make_float4(0.f, 0.f, 0.f, 0.f);
#pragma unroll
        for (int i = 0; i < 16; i++) o4[i] = z;
        return;
    }

    extern __shared__ char smem[];
    const uint32_t sb = smem_u32(smem);
    const int lane = tid & 31;
    const int wid  = tid >> 5;
    const int warpM = wid >> 3;   // 0..1  (64 rows each)
    const int warpN = wid & 7;    // 0..7  (32 cols each)

    if (tid < 256)
        reinterpret_cast<float*>(smem + OFF_BIAS)[tid] = appB[tid] + stB[tid];

    // ldmatrix per-lane constants
    const uint32_t segBase = (uint32_t)(lane >> 4) * 16;
    uint32_t a_row128[4], a_xor[4];
#pragma unroll
    for (int mi = 0; mi < 4; mi++) {
        int r = warpM * 64 + mi * 16 + (lane & 15);
        a_row128[mi] = (uint32_t)r * 128;
        a_xor[mi]    = (uint32_t)(r & 7) << 4;
    }
    uint32_t b_row128[2], b_xor[2];
#pragma unroll
    for (int ng = 0; ng < 2; ng++) {
        int r = warpN * 32 + ng * 16 + (lane & 15);
        b_row128[ng] = (uint32_t)r * 128;
        b_xor[ng]    = (uint32_t)(r & 7) << 4;
    }

    // A-load mapping: 4 threads per row, 16 k each
    const int arow = tid >> 2;
    const int akb  = (tid & 3) * 16;
    const int asrc = g_idx[rowBase + arow];

    float acc[4][4][4];
#pragma unroll
    for (int mi = 0; mi < 4; mi++)
#pragma unroll
        for (int ni = 0; ni < 4; ni++)
#pragma unroll
            for (int q = 0; q < 4; q++) acc[mi][ni][q] = 0.0f;

    float v[16];   // A pipeline regs

    auto loadB = [&](int c, uint32_t bst) {
        const char* srcH = reinterpret_cast<const char*>(g_Bhi) + (size_t)c * 32768;
        const char* srcL = reinterpret_cast<const char*>(g_Blo) + (size_t)c * 32768;
        uint32_t dH = sb + bst + tid * 16;
        uint32_t dL = sb + bst + 32768 + tid * 16;
#pragma unroll
        for (int i = 0; i < 4; i++) {
            cp16(dH + i * 8192, srcH + tid * 16 + i * 8192);
            cp16(dL + i * 8192, srcL + tid * 16 + i * 8192);
        }
    };
    auto ldgA = [&](int c) {
        if (c < 8) {
            const float4* s4 = reinterpret_cast<const float4*>(
                emb + (size_t)asrc * 512 + c * 64 + akb);
#pragma unroll
            for (int q = 0; q < 4; q++) {
                float4 f = s4[q];
                v[4 * q + 0] = f.x; v[4 * q + 1] = f.y;
                v[4 * q + 2] = f.z; v[4 * q + 3] = f.w;
            }
        } else {
#pragma unroll
            for (int j = 0; j < 16; j++) {
                int i = akb + j;
                float val = 0.0f;
                if (i == 0)       val = vis[asrc];
                else if (i < 5)   val = bbox[(size_t)asrc * 4 + (i - 1)];
                else if (i < 56)  val = kpts[(size_t)asrc * 51 + (i - 5)];
                v[j] = val;
            }
        }
    };
    auto stsA = [&](uint32_t ast) {
#pragma unroll
        for (int g = 0; g < 2; g++) {
            uint32_t hw[4], lw[4];
#pragma unroll
            for (int p = 0; p < 4; p++)
                split2(v[8 * g + 2 * p], v[8 * g + 2 * p + 1], hw[p], lw[p]);
            uint32_t off = SW128((uint32_t)(arow * 128 + (akb + 8 * g) * 2));
            *reinterpret_cast<uint4*>(smem + ast + off) =
                make_uint4(hw[0], hw[1], hw[2], hw[3]);
            *reinterpret_cast<uint4*>(smem + ast + 16384 + off) =
                make_uint4(lw[0], lw[1], lw[2], lw[3]);
        }
    };

    // ---- prologue ----
    loadB(0, B_BASE); cp_commit();
    ldgA(0);
    stsA(0);                 // one-time exposed latency
    ldgA(1);

    // ---- mainloop ----
    for (int c = 0; c < NCHUNK; c++) {
        const uint32_t aSt = (uint32_t)(c & 1) * A_STAGE_SZ;
        const uint32_t bSt = B_BASE + (uint32_t)(c & 1) * B_STAGE_SZ;

        cp_wait<0>();            // B(c) resident
        __syncthreads();         // A(c) visible
        if (c + 1 < NCHUNK)
            loadB(c + 1, B_BASE + (uint32_t)((c + 1) & 1) * B_STAGE_SZ);
        cp_commit();

        const uint32_t baseA = sb + aSt;
        const uint32_t baseB = sb + bSt;
#pragma unroll
        for (int s = 0; s < 4; s++) {
            const uint32_t sseg = segBase + (uint32_t)s * 32;
            uint32_t bh[2][4], bl[2][4];
#pragma unroll
            for (int ng = 0; ng < 2; ng++) {
                uint32_t rel = b_row128[ng] + (sseg ^ b_xor[ng]);
                ldsm4(bh[ng], baseB + rel);
                ldsm4(bl[ng], baseB + 32768 + rel);
            }
#pragma unroll
            for (int mi = 0; mi < 4; mi++) {
                uint32_t ah[4], al[4];
                uint32_t rel = a_row128[mi] + (sseg ^ a_xor[mi]);
                ldsm4(ah, baseA + rel);
                ldsm4(al, baseA + 16384 + rel);
#pragma unroll
                for (int ng = 0; ng < 2; ng++) {
                    float* d0 = acc[mi][2 * ng];
                    float* d1 = acc[mi][2 * ng + 1];
                    mma16816(d0[0], d0[1], d0[2], d0[3], ah, bh[ng][0], bh[ng][2]);
                    mma16816(d0[0], d0[1], d0[2], d0[3], ah, bl[ng][0], bl[ng][2]);
                    mma16816(d0[0], d0[1], d0[2], d0[3], al, bh[ng][0], bh[ng][2]);
                    mma16816(d1[0], d1[1], d1[2], d1[3], ah, bh[ng][1], bh[ng][3]);
                    mma16816(d1[0], d1[1], d1[2], d1[3], ah, bl[ng][1], bl[ng][3]);
                    mma16816(d1[0], d1[1], d1[2], d1[3], al, bh[ng][1], bh[ng][3]);
                }
            }
        }

        // feed pipeline: STS A(c+1) from regs, refill regs with A(c+2)
        if (c + 1 < NCHUNK) {
            stsA((uint32_t)((c + 1) & 1) * A_STAGE_SZ);
            if (c + 2 < NCHUNK) ldgA(c + 2);
        }
    }

    // ---- epilogue: bias + permuted scatter store (zeros for inactive rows) ----
    const float* biasS = reinterpret_cast<const float*>(smem + OFF_BIAS);
    const int lr = lane >> 2;
    const int lc = (lane & 3) * 2;
#pragma unroll
    for (int mi = 0; mi < 4; mi++) {
#pragma unroll
        for (int dh = 0; dh < 2; dh++) {
            int rloc = warpM * 64 + mi * 16 + lr + dh * 8;
            int gr = rowBase + rloc;
            int realrow = g_idx[gr];
            float* orow = out + (size_t)realrow * 256;
            if (gr < na) {
#pragma unroll
                for (int ni = 0; ni < 4; ni++) {
                    int cl = warpN * 32 + ni * 8 + lc;
                    float2 w;
                    w.x = acc[mi][ni][2 * dh + 0] + biasS[cl];
                    w.y = acc[mi][ni][2 * dh + 1] + biasS[cl + 1];
                    *reinterpret_cast<float2*>(orow + cl) = w;
                }
            } else {
#pragma unroll
                for (int ni = 0; ni < 4; ni++) {
                    int cl = warpN * 32 + ni * 8 + lc;
                    *reinterpret_cast<float2*>(orow + cl) = make_float2(0.f, 0.f);
                }
            }
        }
    }
}

// ---------------- launch ----------------
extern "C" void kernel_launch(void* const* d_in, const int* in_sizes, int n_in,
                              void* d_out, int out_size) {
    const float* emb  = (const float*)d_in[0];
    const float* vis  = (const float*)d_in[1];
    const float* bbox = (const float*)d_in[2];
    const float* kpts = (const float*)d_in[3];
    const int*   mask = (const int*)d_in[4];
    const float* appW = (const float*)d_in[5];
    const float* appB = (const float*)d_in[6];
    const float* stW  = (const float*)d_in[7];
    const float* stB  = (const float*)d_in[8];

    static int configured = 0;
    if (!configured) {
        cudaFuncSetAttribute(seplin_mma, cudaFuncAttributeMaxDynamicSharedMemorySize,
                             SMEM_TOTAL);
        configured = 1;
    }

    k_prep1<<<NCHUNK + 256, 256>>>(appW, stW, mask);
    k_prep2<<<256, 256>>>(mask);
    seplin_mma<<<GRID_M, NTHR, SMEM_TOTAL>>>(emb, vis, bbox, kpts,
                                             appB, stB, (float*)d_out);
    (void)in_sizes; (void)n_in; (void)out_size;
}